// round 2
// baseline (speedup 1.0000x reference)
#include <cuda_runtime.h>

#define BB 64
#define PP 8732
#define CC 81
#define OO 32

// ---------------- scratch (static device globals; no allocation) ----------------
__device__ float g_ov[BB*PP];
__device__ int   g_oi[BB*PP];
__device__ unsigned g_key[BB*PP];     // orderable-uint CE keys
__device__ unsigned long long g_bestkey[BB*OO];
__device__ float g_loc_sum;
__device__ int   g_npos;
__device__ float g_cepos;
__device__ float g_hard;
__device__ int   g_done;

// ---------------- helpers ----------------
__device__ __forceinline__ unsigned order_key(float f) {
    unsigned u = __float_as_uint(f);
    return (u & 0x80000000u) ? ~u : (u | 0x80000000u);
}
__device__ __forceinline__ float key_val(unsigned u) {
    u = (u & 0x80000000u) ? (u & 0x7FFFFFFFu) : ~u;
    return __uint_as_float(u);
}

// ---------------- k0: zero accumulators ----------------
__global__ void k0_init() {
    int t = blockIdx.x * blockDim.x + threadIdx.x;
    if (t < BB*OO) g_bestkey[t] = 0ULL;
    if (t == 0) { g_loc_sum = 0.f; g_npos = 0; g_cepos = 0.f; g_hard = 0.f; g_done = 0; }
}

// ---------------- k1: IoU matching (guarded smem atomicMax, no shuffles) ----------------
__global__ void k1_match(const float* __restrict__ tb, const float* __restrict__ pbx) {
    int b = blockIdx.y;
    int p = blockIdx.x * 256 + threadIdx.x;
    __shared__ float sx0[OO], sy0[OO], sx1[OO], sy1[OO], sarea[OO];
    __shared__ unsigned long long sbest[OO];
    if (threadIdx.x < OO) {
        const float* t4 = tb + (size_t)(b*OO + threadIdx.x) * 4;
        float x0 = t4[0], y0 = t4[1], x1 = t4[2], y1 = t4[3];
        sx0[threadIdx.x] = x0; sy0[threadIdx.x] = y0;
        sx1[threadIdx.x] = x1; sy1[threadIdx.x] = y1;
        sarea[threadIdx.x] = (x1 - x0) * (y1 - y0);
        sbest[threadIdx.x] = 0ULL;
    }
    __syncthreads();

    bool valid = (p < PP);
    float bx0 = 0, by0 = 0, bx1 = 0, by1 = 0, areab = 0;
    if (valid) {
        const float* pr = pbx + (size_t)p * 4;
        float cx = pr[0], cy = pr[1], w = pr[2], h = pr[3];
        bx0 = cx - 0.5f * w; bx1 = cx + 0.5f * w;
        by0 = cy - 0.5f * h; by1 = cy + 0.5f * h;
        areab = w * h;
    }
    float bestv = -1.f; int besti = 0;
    if (valid) {
        unsigned plow = 0xFFFFFFFFu - (unsigned)p;   // smaller p -> bigger low bits
        #pragma unroll 4
        for (int o = 0; o < OO; o++) {
            float lx = fmaxf(sx0[o], bx0), ly = fmaxf(sy0[o], by0);
            float rx = fminf(sx1[o], bx1), ry = fminf(sy1[o], by1);
            float iw = fmaxf(rx - lx, 0.f), ih = fmaxf(ry - ly, 0.f);
            float inter = iw * ih;
            float uni = sarea[o] + areab - inter;
            float iou = __fdividef(inter, uni);            // iou >= 0 always
            if (iou > bestv) { bestv = iou; besti = o; }   // first-index tiebreak
            unsigned long long key =
                ((unsigned long long)(__float_as_uint(iou) | 0x80000000u) << 32)
                | (unsigned long long)plow;
            if (key > sbest[o]) atomicMax(&sbest[o], key); // guard makes atomic rare
        }
        g_ov[b*PP + p] = bestv;
        g_oi[b*PP + p] = besti;
    }
    __syncthreads();
    if (threadIdx.x < OO) atomicMax(&g_bestkey[b*OO + threadIdx.x], sbest[threadIdx.x]);
}

// ---------------- k2: sequential scatter (last write wins, per batch) ----------------
__global__ void k2_scatter() {
    int b = threadIdx.x;
    if (b < BB) {
        for (int o = 0; o < OO; o++) {
            unsigned long long key = g_bestkey[b*OO + o];
            unsigned p = 0xFFFFFFFFu - (unsigned)(key & 0xFFFFFFFFull);
            g_oi[b*PP + p] = o;
            g_ov[b*PP + p] = 1.0f;
        }
    }
}

// ---------------- k34: fused labels + loc loss + cross-entropy ----------------
// warp per row (grid-stride). No max-subtraction: scores ~N(0,1), exp safe.
__global__ void k34_ce(const float* __restrict__ pred, const float* __restrict__ scores,
                       const float* __restrict__ tb, const int* __restrict__ tc,
                       const float* __restrict__ pbx) {
    int lane = threadIdx.x & 31;
    int warp = (blockIdx.x * blockDim.x + threadIdx.x) >> 5;
    int nwarps = (gridDim.x * blockDim.x) >> 5;
    float acc = 0.f, l1 = 0.f; int cnt = 0;
    #pragma unroll 2
    for (int idx = warp; idx < BB*PP; idx += nwarps) {
        const float* s = scores + (size_t)idx * CC;
        float s0 = __ldg(s + lane);
        float s1 = __ldg(s + lane + 32);
        float s2 = (lane < CC - 64) ? __ldg(s + lane + 64) : 0.f;
        float e = __expf(s0) + __expf(s1) + ((lane < CC - 64) ? __expf(s2) : 0.f);
        #pragma unroll
        for (int off = 16; off; off >>= 1) e += __shfl_xor_sync(0xffffffffu, e, off);
        int lab = 0, oi = 0;
        if (lane == 0) {
            float ov = g_ov[idx];
            oi = g_oi[idx];
            int b = idx / PP;
            lab = (ov < 0.5f) ? 0 : tc[b*OO + oi];
        }
        lab = __shfl_sync(0xffffffffu, lab, 0);
        float sl;
        if (lab < 32)      sl = __shfl_sync(0xffffffffu, s0, lab);
        else if (lab < 64) sl = __shfl_sync(0xffffffffu, s1, lab - 32);
        else               sl = __shfl_sync(0xffffffffu, s2, lab - 64);
        float ce = __logf(e) - sl;
        if (lane == 0) {
            g_key[idx] = order_key(ce);
            if (lab != 0) {
                acc += ce; cnt++;
                int b = idx / PP;
                int p = idx - b*PP;
                const float* t4 = tb + (size_t)(b*OO + oi) * 4;
                float x0 = t4[0], y0 = t4[1], x1 = t4[2], y1 = t4[3];
                const float* pr = pbx + (size_t)p * 4;
                float pcx = pr[0], pcy = pr[1], pw = pr[2], ph = pr[3];
                float gcx = ((x0 + x1) * 0.5f - pcx) * 10.f / pw;
                float gcy = ((y0 + y1) * 0.5f - pcy) * 10.f / ph;
                float gw  = logf((x1 - x0) / pw) * 5.f;
                float gh  = logf((y1 - y0) / ph) * 5.f;
                const float* pd = pred + (size_t)idx * 4;
                l1 += fabsf(pd[0]-gcx) + fabsf(pd[1]-gcy) + fabsf(pd[2]-gw) + fabsf(pd[3]-gh);
            }
        }
    }
    // block reduce (only lane0 of each warp holds values)
    __shared__ float sacc[8], sl1[8]; __shared__ int scnt[8];
    if (lane == 0) { sacc[threadIdx.x >> 5] = acc; sl1[threadIdx.x >> 5] = l1; scnt[threadIdx.x >> 5] = cnt; }
    __syncthreads();
    if (threadIdx.x == 0) {
        float a = 0.f, l = 0.f; int c = 0;
        #pragma unroll
        for (int i = 0; i < 8; i++) { a += sacc[i]; l += sl1[i]; c += scnt[i]; }
        if (a != 0.f) atomicAdd(&g_cepos, a);
        if (l != 0.f) atomicAdd(&g_loc_sum, l);
        if (c)        atomicAdd(&g_npos, c);
    }
}

// ---------------- k5: per-row top-k sum via exact radix select + finalize ----------------
// one block per row (B rows), 1024 threads. k = 3*n_pos (global).
__global__ void k5_select(float* __restrict__ out) {
    __shared__ unsigned skeys[PP];
    __shared__ int bins[256];
    __shared__ unsigned sh_pref;
    __shared__ int sh_rem;
    __shared__ float swsum[32];
    __shared__ int swcnt[32];
    int r = blockIdx.x;
    int tid = threadIdx.x;
    const int bd = 1024;
    int lane = tid & 31, wid = tid >> 5;
    for (int p = tid; p < PP; p += bd) skeys[p] = g_key[(size_t)r*PP + p];
    __syncthreads();
    int np = g_npos;
    long long k = 3LL * (long long)np;
    const int NITER = (PP + bd - 1) / bd;   // padded iteration count (warp-uniform)

    float total = 0.f;  // this row's hard-neg contribution (valid on tid 0)
    if (k >= PP) {
        float s = 0.f;
        for (int p = tid; p < PP; p += bd) s += key_val(skeys[p]);
        #pragma unroll
        for (int off = 16; off; off >>= 1) s += __shfl_xor_sync(0xffffffffu, s, off);
        if (lane == 0) swsum[wid] = s;
        __syncthreads();
        if (tid == 0) { for (int i = 0; i < bd/32; i++) total += swsum[i]; }
    } else if (k > 0) {
        unsigned prefix = 0; int rem = (int)k;
        for (int shift = 24; shift >= 0; shift -= 8) {
            if (tid < 256) bins[tid] = 0;
            __syncthreads();
            unsigned hi_mask = (shift == 24) ? 0u : (0xFFFFFFFFu << (shift + 8));
            for (int it = 0; it < NITER; it++) {
                int p = tid + it * bd;
                bool in = (p < PP);
                unsigned key = in ? skeys[p] : 0u;
                bool act = in && ((key & hi_mask) == prefix);
                unsigned bm = __ballot_sync(0xffffffffu, act);
                if (act) {
                    unsigned bin = (key >> shift) & 255u;
                    unsigned peers = __match_any_sync(bm, bin);
                    int leader = __ffs(peers) - 1;
                    if (lane == leader) atomicAdd(&bins[bin], __popc(peers));
                }
            }
            __syncthreads();
            if (tid == 0) {
                int cum = 0;
                for (int bi = 255; bi >= 0; bi--) {
                    int c = bins[bi];
                    if (cum + c >= rem) { sh_rem = rem - cum; sh_pref = prefix | ((unsigned)bi << shift); break; }
                    cum += c;
                }
            }
            __syncthreads();
            prefix = sh_pref; rem = sh_rem;
            __syncthreads();
        }
        unsigned kth = prefix;  // exact k-th largest key
        float sumv = 0.f; int cgt = 0;
        for (int p = tid; p < PP; p += bd) {
            unsigned key = skeys[p];
            if (key > kth) { sumv += key_val(key); cgt++; }
        }
        #pragma unroll
        for (int off = 16; off; off >>= 1) {
            sumv += __shfl_xor_sync(0xffffffffu, sumv, off);
            cgt  += __shfl_xor_sync(0xffffffffu, cgt, off);
        }
        if (lane == 0) { swsum[wid] = sumv; swcnt[wid] = cgt; }
        __syncthreads();
        if (tid == 0) {
            float t = 0.f; int c = 0;
            for (int i = 0; i < bd/32; i++) { t += swsum[i]; c += swcnt[i]; }
            total = t + (float)(k - c) * key_val(kth);   // exact tie handling
        }
    }

    if (tid == 0) {
        if (total != 0.f) atomicAdd(&g_hard, total);
        __threadfence();
        int ticket = atomicAdd(&g_done, 1);
        if (ticket == BB - 1) {
            float hard = atomicAdd(&g_hard, 0.f);   // acquire-ish read after all adds
            float npf = (float)np;
            out[0] = g_loc_sum / (npf * 4.f) + (g_cepos + hard) / npf;
        }
    }
}

// ---------------- launch ----------------
extern "C" void kernel_launch(void* const* d_in, const int* in_sizes, int n_in,
                              void* d_out, int out_size) {
    const float* pred_boxes   = (const float*)d_in[0];
    const float* pred_scores  = (const float*)d_in[1];
    const float* true_boxes   = (const float*)d_in[2];
    const int*   true_classes = (const int*)d_in[3];
    const float* pboxes       = (const float*)d_in[4];
    float* out = (float*)d_out;
    (void)in_sizes; (void)n_in; (void)out_size;

    k0_init<<<2, 1024>>>();
    dim3 g1((PP + 255) / 256, BB);
    k1_match<<<g1, 256>>>(true_boxes, pboxes);
    k2_scatter<<<1, 64>>>();
    k34_ce<<<8192, 256>>>(pred_boxes, pred_scores, true_boxes, true_classes, pboxes);
    k5_select<<<BB, 1024>>>(out);
}

// round 3
// speedup vs baseline: 1.2797x; 1.2797x over previous
#include <cuda_runtime.h>

#define BB 64
#define PP 8732
#define CC 81
#define OO 32

// ---------------- scratch (static device globals; no allocation) ----------------
__device__ float g_ov[BB*PP];
__device__ int   g_oi[BB*PP];
__device__ unsigned g_key[BB*PP];     // orderable-uint CE keys
__device__ unsigned long long g_bestkey[BB*OO];
__device__ float g_loc_sum;
__device__ int   g_npos;
__device__ float g_cepos;
__device__ float g_hard;
__device__ int   g_done;

// ---------------- helpers ----------------
__device__ __forceinline__ unsigned order_key(float f) {
    unsigned u = __float_as_uint(f);
    return (u & 0x80000000u) ? ~u : (u | 0x80000000u);
}
__device__ __forceinline__ float key_val(unsigned u) {
    u = (u & 0x80000000u) ? (u & 0x7FFFFFFFu) : ~u;
    return __uint_as_float(u);
}

// ---------------- k0: zero accumulators ----------------
__global__ void k0_init() {
    int t = blockIdx.x * blockDim.x + threadIdx.x;
    if (t < BB*OO) g_bestkey[t] = 0ULL;
    if (t == 0) { g_loc_sum = 0.f; g_npos = 0; g_cepos = 0.f; g_hard = 0.f; g_done = 0; }
}

// ---------------- k1: IoU matching (R1 shuffle-reduce version, no contended atomics) ----------------
__global__ void k1_match(const float* __restrict__ tb, const float* __restrict__ pbx) {
    int b = blockIdx.y;
    int p = blockIdx.x * 256 + threadIdx.x;
    __shared__ float sx0[OO], sy0[OO], sx1[OO], sy1[OO], sarea[OO];
    __shared__ unsigned long long sbest[OO];
    if (threadIdx.x < OO) {
        const float* t4 = tb + (size_t)(b*OO + threadIdx.x) * 4;
        float x0 = t4[0], y0 = t4[1], x1 = t4[2], y1 = t4[3];
        sx0[threadIdx.x] = x0; sy0[threadIdx.x] = y0;
        sx1[threadIdx.x] = x1; sy1[threadIdx.x] = y1;
        sarea[threadIdx.x] = (x1 - x0) * (y1 - y0);
        sbest[threadIdx.x] = 0ULL;
    }
    __syncthreads();

    bool valid = (p < PP);
    float bx0 = 0, by0 = 0, bx1 = 0, by1 = 0, areab = 0;
    if (valid) {
        const float* pr = pbx + (size_t)p * 4;
        float cx = pr[0], cy = pr[1], w = pr[2], h = pr[3];
        bx0 = cx - 0.5f * w; bx1 = cx + 0.5f * w;
        by0 = cy - 0.5f * h; by1 = cy + 0.5f * h;
        areab = w * h;
    }
    float bestv = -1.f; int besti = 0;
    int lane = threadIdx.x & 31;
    #pragma unroll 4
    for (int o = 0; o < OO; o++) {
        unsigned long long key = 0ULL;
        if (valid) {
            float lx = fmaxf(sx0[o], bx0), ly = fmaxf(sy0[o], by0);
            float rx = fminf(sx1[o], bx1), ry = fminf(sy1[o], by1);
            float iw = fmaxf(rx - lx, 0.f), ih = fmaxf(ry - ly, 0.f);
            float inter = iw * ih;
            float uni = sarea[o] + areab - inter;
            float iou = __fdividef(inter, uni);           // iou >= 0 always
            if (iou > bestv) { bestv = iou; besti = o; }  // first-index tiebreak
            key = ((unsigned long long)(__float_as_uint(iou) | 0x80000000u) << 32)
                | (unsigned long long)(0xFFFFFFFFu - (unsigned)p); // smaller p wins ties
        }
        #pragma unroll
        for (int off = 16; off; off >>= 1) {
            unsigned long long o2 = __shfl_down_sync(0xffffffffu, key, off);
            if (o2 > key) key = o2;
        }
        if (lane == 0) atomicMax(&sbest[o], key);   // 8 atomics per object per block only
    }
    __syncthreads();
    if (threadIdx.x < OO) atomicMax(&g_bestkey[b*OO + threadIdx.x], sbest[threadIdx.x]);
    if (valid) { g_ov[b*PP + p] = bestv; g_oi[b*PP + p] = besti; }
}

// ---------------- k2: sequential scatter (last write wins, per batch) ----------------
__global__ void k2_scatter() {
    int b = threadIdx.x;
    if (b < BB) {
        for (int o = 0; o < OO; o++) {
            unsigned long long key = g_bestkey[b*OO + o];
            unsigned p = 0xFFFFFFFFu - (unsigned)(key & 0xFFFFFFFFull);
            g_oi[b*PP + p] = o;
            g_ov[b*PP + p] = 1.0f;
        }
    }
}

// ---------------- k34: fused labels + loc loss + CE, smem-tiled thread-per-row ----------------
// 128 threads, 128 rows per block. Tile = contiguous 41472B span -> coalesced float4 load,
// then each thread owns one full row in smem (stride 81 words = conflict-free).
#define RPB 128
#define TPB 128
#define TILE_F4 ((RPB * CC) / 4)   // 2592 float4 per block (RPB*CC = 10368, divisible by 4)

__global__ void __launch_bounds__(TPB) k34_ce(
        const float* __restrict__ pred, const float* __restrict__ scores,
        const float* __restrict__ tb, const int* __restrict__ tc,
        const float* __restrict__ pbx) {
    __shared__ float s[RPB * CC];           // 41472 B
    int tid = threadIdx.x;
    size_t base_f4 = (size_t)blockIdx.x * TILE_F4;
    const float4* src = (const float4*)scores + base_f4;
    float4* dst = (float4*)s;
    #pragma unroll 4
    for (int i = tid; i < TILE_F4; i += TPB) dst[i] = __ldg(src + i);
    __syncthreads();

    int idx = blockIdx.x * RPB + tid;       // global row (always < BB*PP: 4366*128 exact)
    const float* my = s + tid * CC;

    // sum of exp (no max-subtraction: scores ~N(0,1))
    float a0 = 0.f, a1 = 0.f, a2 = 0.f, a3 = 0.f;
    #pragma unroll
    for (int j = 0; j < 80; j += 4) {
        a0 += __expf(my[j]);
        a1 += __expf(my[j+1]);
        a2 += __expf(my[j+2]);
        a3 += __expf(my[j+3]);
    }
    a0 += __expf(my[80]);
    float e = (a0 + a1) + (a2 + a3);

    float ov = g_ov[idx];
    int   oi = g_oi[idx];
    int b = idx / PP;
    int p = idx - b * PP;
    int lab = (ov < 0.5f) ? 0 : __ldg(tc + b*OO + oi);

    float ce = __logf(e) - my[lab];
    g_key[idx] = order_key(ce);

    float acc = 0.f, l1 = 0.f; int cnt = 0;
    if (lab != 0) {
        acc = ce; cnt = 1;
        const float* t4 = tb + (size_t)(b*OO + oi) * 4;
        float x0 = __ldg(t4), y0 = __ldg(t4+1), x1 = __ldg(t4+2), y1 = __ldg(t4+3);
        const float* pr = pbx + (size_t)p * 4;
        float pcx = __ldg(pr), pcy = __ldg(pr+1), pw = __ldg(pr+2), ph = __ldg(pr+3);
        float gcx = ((x0 + x1) * 0.5f - pcx) * 10.f / pw;
        float gcy = ((y0 + y1) * 0.5f - pcy) * 10.f / ph;
        float gw  = logf((x1 - x0) / pw) * 5.f;
        float gh  = logf((y1 - y0) / ph) * 5.f;
        const float* pd = pred + (size_t)idx * 4;
        l1 = fabsf(pd[0]-gcx) + fabsf(pd[1]-gcy) + fabsf(pd[2]-gw) + fabsf(pd[3]-gh);
    }

    // block reduce
    int lane = tid & 31, wid = tid >> 5;
    #pragma unroll
    for (int off = 16; off; off >>= 1) {
        acc += __shfl_xor_sync(0xffffffffu, acc, off);
        l1  += __shfl_xor_sync(0xffffffffu, l1, off);
        cnt += __shfl_xor_sync(0xffffffffu, cnt, off);
    }
    __shared__ float racc[4], rl1[4]; __shared__ int rcnt[4];
    if (lane == 0) { racc[wid] = acc; rl1[wid] = l1; rcnt[wid] = cnt; }
    __syncthreads();
    if (tid == 0) {
        float a = racc[0]+racc[1]+racc[2]+racc[3];
        float l = rl1[0]+rl1[1]+rl1[2]+rl1[3];
        int   c = rcnt[0]+rcnt[1]+rcnt[2]+rcnt[3];
        if (a != 0.f) atomicAdd(&g_cepos, a);
        if (l != 0.f) atomicAdd(&g_loc_sum, l);
        if (c)        atomicAdd(&g_npos, c);
    }
}

// ---------------- k5: per-row top-k sum via exact radix select + fused finalize ----------------
// one block per row (B rows), 512 threads. k = 3*n_pos (global scalar).
__global__ void k5_select(float* __restrict__ out) {
    __shared__ unsigned skeys[PP];
    __shared__ int bins[256];
    __shared__ unsigned sh_pref;
    __shared__ int sh_rem;
    __shared__ float swsum[16];
    __shared__ int swcnt[16];
    int r = blockIdx.x;
    int tid = threadIdx.x;
    const int bd = 512;
    int lane = tid & 31, wid = tid >> 5;
    for (int p = tid; p < PP; p += bd) skeys[p] = g_key[(size_t)r*PP + p];
    __syncthreads();
    int np = g_npos;
    long long k = 3LL * (long long)np;

    float total = 0.f;  // this row's hard-neg contribution (valid on tid 0)
    if (k >= PP) {
        float sv = 0.f;
        for (int p = tid; p < PP; p += bd) sv += key_val(skeys[p]);
        #pragma unroll
        for (int off = 16; off; off >>= 1) sv += __shfl_xor_sync(0xffffffffu, sv, off);
        if (lane == 0) swsum[wid] = sv;
        __syncthreads();
        if (tid == 0) for (int i = 0; i < bd/32; i++) total += swsum[i];
    } else if (k > 0) {
        unsigned prefix = 0; int rem = (int)k;
        for (int shift = 24; shift >= 0; shift -= 8) {
            if (tid < 256) bins[tid] = 0;
            __syncthreads();
            unsigned hi_mask = (shift == 24) ? 0u : (0xFFFFFFFFu << (shift + 8));
            for (int p = tid; p < PP; p += bd) {
                unsigned key = skeys[p];
                if ((key & hi_mask) == prefix) atomicAdd(&bins[(key >> shift) & 255], 1);
            }
            __syncthreads();
            if (tid == 0) {
                int cum = 0;
                for (int bi = 255; bi >= 0; bi--) {
                    int c = bins[bi];
                    if (cum + c >= rem) { sh_rem = rem - cum; sh_pref = prefix | ((unsigned)bi << shift); break; }
                    cum += c;
                }
            }
            __syncthreads();
            prefix = sh_pref; rem = sh_rem;
            __syncthreads();
        }
        unsigned kth = prefix;  // exact k-th largest key
        float sumv = 0.f; int cgt = 0;
        for (int p = tid; p < PP; p += bd) {
            unsigned key = skeys[p];
            if (key > kth) { sumv += key_val(key); cgt++; }
        }
        #pragma unroll
        for (int off = 16; off; off >>= 1) {
            sumv += __shfl_xor_sync(0xffffffffu, sumv, off);
            cgt  += __shfl_xor_sync(0xffffffffu, cgt, off);
        }
        if (lane == 0) { swsum[wid] = sumv; swcnt[wid] = cgt; }
        __syncthreads();
        if (tid == 0) {
            float t = 0.f; int c = 0;
            for (int i = 0; i < bd/32; i++) { t += swsum[i]; c += swcnt[i]; }
            total = t + (float)(k - c) * key_val(kth);   // exact tie handling
        }
    }

    if (tid == 0) {
        if (total != 0.f) atomicAdd(&g_hard, total);
        __threadfence();
        int ticket = atomicAdd(&g_done, 1);
        if (ticket == BB - 1) {                          // last block finalizes
            float hard = atomicAdd(&g_hard, 0.f);
            float npf = (float)np;
            out[0] = g_loc_sum / (npf * 4.f) + (g_cepos + hard) / npf;
        }
    }
}

// ---------------- launch ----------------
extern "C" void kernel_launch(void* const* d_in, const int* in_sizes, int n_in,
                              void* d_out, int out_size) {
    const float* pred_boxes   = (const float*)d_in[0];
    const float* pred_scores  = (const float*)d_in[1];
    const float* true_boxes   = (const float*)d_in[2];
    const int*   true_classes = (const int*)d_in[3];
    const float* pboxes       = (const float*)d_in[4];
    float* out = (float*)d_out;
    (void)in_sizes; (void)n_in; (void)out_size;

    k0_init<<<2, 1024>>>();
    dim3 g1((PP + 255) / 256, BB);
    k1_match<<<g1, 256>>>(true_boxes, pboxes);
    k2_scatter<<<1, 64>>>();
    k34_ce<<<(BB*PP)/RPB, TPB>>>(pred_boxes, pred_scores, true_boxes, true_classes, pboxes);
    k5_select<<<BB, 512>>>(out);
}

// round 5
// speedup vs baseline: 1.4332x; 1.1200x over previous
#include <cuda_runtime.h>

#define BB 64
#define PP 8732
#define CC 81
#define OO 32
#define NBLK1 35   // ceil(PP/256)

// ---------------- scratch (static device globals; no allocation) ----------------
__device__ float g_ov[BB*PP];
__device__ int   g_oi[BB*PP];
__device__ unsigned g_key[BB*PP];                  // orderable-uint CE keys
__device__ unsigned long long g_part[NBLK1*BB*OO]; // per-block argmax partials
__device__ float g_loc_sum;
__device__ int   g_npos;
__device__ float g_cepos;
__device__ float g_hard;
__device__ int   g_done;

// ---------------- helpers ----------------
__device__ __forceinline__ unsigned order_key(float f) {
    unsigned u = __float_as_uint(f);
    return (u & 0x80000000u) ? ~u : (u | 0x80000000u);
}
__device__ __forceinline__ float key_val(unsigned u) {
    u = (u & 0x80000000u) ? (u & 0x7FFFFFFFu) : ~u;
    return __uint_as_float(u);
}

// ---------------- k1: IoU matching, block-local partials (no global atomics) ----------------
// grid (NBLK1, BB) x 256. float shuffle-max + ballot for per-warp argmax.
__global__ void k1_match(const float* __restrict__ tb, const float* __restrict__ pbx) {
    int b = blockIdx.y;
    int p = blockIdx.x * 256 + threadIdx.x;
    __shared__ float sx0[OO], sy0[OO], sx1[OO], sy1[OO], sarea[OO];
    __shared__ unsigned long long sbest[OO];
    if (threadIdx.x < OO) {
        const float* t4 = tb + (size_t)(b*OO + threadIdx.x) * 4;
        float x0 = t4[0], y0 = t4[1], x1 = t4[2], y1 = t4[3];
        sx0[threadIdx.x] = x0; sy0[threadIdx.x] = y0;
        sx1[threadIdx.x] = x1; sy1[threadIdx.x] = y1;
        sarea[threadIdx.x] = (x1 - x0) * (y1 - y0);
        sbest[threadIdx.x] = 0ULL;
    }
    __syncthreads();

    bool valid = (p < PP);
    float bx0 = 0, by0 = 0, bx1 = 0, by1 = 0, areab = 0;
    if (valid) {
        const float* pr = pbx + (size_t)p * 4;
        float cx = pr[0], cy = pr[1], w = pr[2], h = pr[3];
        bx0 = cx - 0.5f * w; bx1 = cx + 0.5f * w;
        by0 = cy - 0.5f * h; by1 = cy + 0.5f * h;
        areab = w * h;
    }
    float bestv = -1.f; int besti = 0;
    int lane = threadIdx.x & 31;
    unsigned plow = 0xFFFFFFFFu - (unsigned)p;      // smaller p -> larger low bits
    #pragma unroll 4
    for (int o = 0; o < OO; o++) {
        float iou = -1.f;
        if (valid) {
            float lx = fmaxf(sx0[o], bx0), ly = fmaxf(sy0[o], by0);
            float rx = fminf(sx1[o], bx1), ry = fminf(sy1[o], by1);
            float iw = fmaxf(rx - lx, 0.f), ih = fmaxf(ry - ly, 0.f);
            float inter = iw * ih;
            float uni = sarea[o] + areab - inter;
            iou = __fdividef(inter, uni);            // iou >= 0 always
            if (iou > bestv) { bestv = iou; besti = o; }  // first-index tiebreak
        }
        // warp float max reduce (all lanes participate)
        float v = iou;
        #pragma unroll
        for (int off = 16; off; off >>= 1) v = fmaxf(v, __shfl_xor_sync(0xffffffffu, v, off));
        unsigned m = __ballot_sync(0xffffffffu, iou == v);
        int src = __ffs(m) - 1;                      // lowest lane = smallest prior
        if (lane == src && v >= 0.f) {
            unsigned long long key =
                ((unsigned long long)(__float_as_uint(v) | 0x80000000u) << 32)
                | (unsigned long long)plow;
            atomicMax(&sbest[o], key);               // <=8 per object per block
        }
    }
    if (valid) { g_ov[b*PP + p] = bestv; g_oi[b*PP + p] = besti; }
    __syncthreads();
    if (threadIdx.x < OO)
        g_part[((size_t)blockIdx.x * BB + b) * OO + threadIdx.x] = sbest[threadIdx.x];
}

// ---------------- k2: reduce partials + sequential scatter + zero scalars ----------------
// grid 2 x 1024: warp = batch, lane = object.
// FIX (R4 crash): all 32 lanes execute every __shfl_sync; only lane 0 stores.
__global__ void k2_scatter() {
    if (blockIdx.x == 0 && threadIdx.x == 0) {
        g_loc_sum = 0.f; g_npos = 0; g_cepos = 0.f; g_hard = 0.f; g_done = 0;
    }
    int w = (blockIdx.x * blockDim.x + threadIdx.x) >> 5;
    int o = threadIdx.x & 31;
    if (w >= BB) return;                 // whole warps retire together (w is warp-uniform)
    int b = w;
    unsigned long long best = 0ULL;
    #pragma unroll 5
    for (int i = 0; i < NBLK1; i++) {
        unsigned long long k = g_part[((size_t)i * BB + b) * OO + o];
        if (k > best) best = k;
    }
    // sequential scatter (last write wins over o, per batch); all lanes shuffle
    #pragma unroll
    for (int j = 0; j < OO; j++) {
        unsigned long long key = __shfl_sync(0xffffffffu, best, j);
        if (o == 0) {
            unsigned p = 0xFFFFFFFFu - (unsigned)(key & 0xFFFFFFFFull);
            if (p < PP) {                // defensive (key always nonzero in practice)
                g_oi[b*PP + p] = j;
                g_ov[b*PP + p] = 1.0f;
            }
        }
    }
}

// ---------------- k34: fused labels + loc loss + CE; 2 threads per row ----------------
#define RPB 128
#define TPB 256
#define TILE_F4 ((RPB * CC) / 4)   // 2592 float4 per block

__global__ void __launch_bounds__(TPB, 5) k34_ce(
        const float* __restrict__ pred, const float* __restrict__ scores,
        const float* __restrict__ tb, const int* __restrict__ tc,
        const float* __restrict__ pbx) {
    __shared__ float s[RPB * CC];           // 41472 B
    int tid = threadIdx.x;
    size_t base_f4 = (size_t)blockIdx.x * TILE_F4;
    const float4* src = (const float4*)scores + base_f4;
    float4* dst = (float4*)s;
    #pragma unroll 4
    for (int i = tid; i < TILE_F4; i += TPB) dst[i] = __ldg(src + i);
    __syncthreads();

    int half = tid & 1;
    int r = tid >> 1;
    int idx = blockIdx.x * RPB + r;
    const float* my = s + r * CC;
    int off0 = half * 40;

    float a0 = 0.f, a1 = 0.f, a2 = 0.f, a3 = 0.f;
    #pragma unroll
    for (int j = 0; j < 40; j += 4) {
        a0 += __expf(my[off0 + j]);
        a1 += __expf(my[off0 + j + 1]);
        a2 += __expf(my[off0 + j + 2]);
        a3 += __expf(my[off0 + j + 3]);
    }
    float e = (a0 + a1) + (a2 + a3);
    if (half) e += __expf(my[80]);
    e += __shfl_xor_sync(0xffffffffu, e, 1);   // pair combine: full row sum-exp

    float acc = 0.f, l1 = 0.f; int cnt = 0;
    if (half == 0) {
        float ov = g_ov[idx];
        int   oi = g_oi[idx];
        int b = idx / PP;
        int p = idx - b * PP;
        int lab = (ov < 0.5f) ? 0 : __ldg(tc + b*OO + oi);
        float ce = __logf(e) - my[lab];
        g_key[idx] = order_key(ce);
        if (lab != 0) {
            acc = ce; cnt = 1;
            const float* t4 = tb + (size_t)(b*OO + oi) * 4;
            float x0 = __ldg(t4), y0 = __ldg(t4+1), x1 = __ldg(t4+2), y1 = __ldg(t4+3);
            const float* pr = pbx + (size_t)p * 4;
            float pcx = __ldg(pr), pcy = __ldg(pr+1), pw = __ldg(pr+2), ph = __ldg(pr+3);
            float gcx = ((x0 + x1) * 0.5f - pcx) * 10.f / pw;
            float gcy = ((y0 + y1) * 0.5f - pcy) * 10.f / ph;
            float gw  = logf((x1 - x0) / pw) * 5.f;
            float gh  = logf((y1 - y0) / ph) * 5.f;
            const float* pd = pred + (size_t)idx * 4;
            l1 = fabsf(pd[0]-gcx) + fabsf(pd[1]-gcy) + fabsf(pd[2]-gw) + fabsf(pd[3]-gh);
        }
    }

    // block reduce (odd threads contribute zeros); all lanes shuffle
    int lane = tid & 31, wid = tid >> 5;
    #pragma unroll
    for (int off = 16; off; off >>= 1) {
        acc += __shfl_xor_sync(0xffffffffu, acc, off);
        l1  += __shfl_xor_sync(0xffffffffu, l1, off);
        cnt += __shfl_xor_sync(0xffffffffu, cnt, off);
    }
    __shared__ float racc[8], rl1[8]; __shared__ int rcnt[8];
    if (lane == 0) { racc[wid] = acc; rl1[wid] = l1; rcnt[wid] = cnt; }
    __syncthreads();
    if (tid == 0) {
        float a = 0.f, l = 0.f; int c = 0;
        #pragma unroll
        for (int i = 0; i < 8; i++) { a += racc[i]; l += rl1[i]; c += rcnt[i]; }
        if (a != 0.f) atomicAdd(&g_cepos, a);
        if (l != 0.f) atomicAdd(&g_loc_sum, l);
        if (c)        atomicAdd(&g_npos, c);
    }
}

// ---------------- k5: per-row top-k via exact radix select + fused finalize ----------------
__global__ void k5_select(float* __restrict__ out) {
    __shared__ unsigned skeys[PP];
    __shared__ int bins[256];
    __shared__ unsigned sh_pref;
    __shared__ int sh_rem;
    __shared__ float swsum[16];
    __shared__ int swcnt[16];
    int r = blockIdx.x;
    int tid = threadIdx.x;
    const int bd = 512;
    const int NITER = (PP + bd - 1) / bd;    // 18 padded iterations (warp-uniform)
    int lane = tid & 31, wid = tid >> 5;
    for (int p = tid; p < PP; p += bd) skeys[p] = g_key[(size_t)r*PP + p];
    __syncthreads();
    int np = g_npos;
    long long k = 3LL * (long long)np;

    float total = 0.f;
    if (k >= PP) {
        float sv = 0.f;
        for (int p = tid; p < PP; p += bd) sv += key_val(skeys[p]);
        #pragma unroll
        for (int off = 16; off; off >>= 1) sv += __shfl_xor_sync(0xffffffffu, sv, off);
        if (lane == 0) swsum[wid] = sv;
        __syncthreads();
        if (tid == 0) for (int i = 0; i < bd/32; i++) total += swsum[i];
    } else if (k > 0) {
        unsigned prefix = 0; int rem = (int)k;
        for (int shift = 24; shift >= 0; shift -= 8) {
            if (tid < 256) bins[tid] = 0;
            __syncthreads();
            unsigned hi_mask = (shift == 24) ? 0u : (0xFFFFFFFFu << (shift + 8));
            for (int it = 0; it < NITER; it++) {
                int p = tid + it * bd;
                bool in = (p < PP);
                unsigned key = in ? skeys[p] : 0u;
                bool act = in && ((key & hi_mask) == prefix);
                unsigned bm = __ballot_sync(0xffffffffu, act);
                if (act) {
                    unsigned bin = (key >> shift) & 255u;
                    unsigned peers = __match_any_sync(bm, bin);
                    int leader = __ffs(peers) - 1;
                    if (lane == leader) atomicAdd(&bins[bin], __popc(peers));
                }
            }
            __syncthreads();
            if (tid == 0) {
                int cum = 0;
                for (int bi = 255; bi >= 0; bi--) {
                    int c = bins[bi];
                    if (cum + c >= rem) { sh_rem = rem - cum; sh_pref = prefix | ((unsigned)bi << shift); break; }
                    cum += c;
                }
            }
            __syncthreads();
            prefix = sh_pref; rem = sh_rem;
            __syncthreads();
        }
        unsigned kth = prefix;  // exact k-th largest key
        float sumv = 0.f; int cgt = 0;
        for (int p = tid; p < PP; p += bd) {
            unsigned key = skeys[p];
            if (key > kth) { sumv += key_val(key); cgt++; }
        }
        #pragma unroll
        for (int off = 16; off; off >>= 1) {
            sumv += __shfl_xor_sync(0xffffffffu, sumv, off);
            cgt  += __shfl_xor_sync(0xffffffffu, cgt, off);
        }
        if (lane == 0) { swsum[wid] = sumv; swcnt[wid] = cgt; }
        __syncthreads();
        if (tid == 0) {
            float t = 0.f; int c = 0;
            for (int i = 0; i < bd/32; i++) { t += swsum[i]; c += swcnt[i]; }
            total = t + (float)(k - c) * key_val(kth);   // exact tie handling
        }
    }

    if (tid == 0) {
        if (total != 0.f) atomicAdd(&g_hard, total);
        __threadfence();
        int ticket = atomicAdd(&g_done, 1);
        if (ticket == BB - 1) {                          // last block finalizes
            float hard = atomicAdd(&g_hard, 0.f);
            float npf = (float)np;
            out[0] = g_loc_sum / (npf * 4.f) + (g_cepos + hard) / npf;
        }
    }
}

// ---------------- launch ----------------
extern "C" void kernel_launch(void* const* d_in, const int* in_sizes, int n_in,
                              void* d_out, int out_size) {
    const float* pred_boxes   = (const float*)d_in[0];
    const float* pred_scores  = (const float*)d_in[1];
    const float* true_boxes   = (const float*)d_in[2];
    const int*   true_classes = (const int*)d_in[3];
    const float* pboxes       = (const float*)d_in[4];
    float* out = (float*)d_out;
    (void)in_sizes; (void)n_in; (void)out_size;

    dim3 g1(NBLK1, BB);
    k1_match<<<g1, 256>>>(true_boxes, pboxes);
    k2_scatter<<<2, 1024>>>();
    k34_ce<<<(BB*PP)/RPB, TPB>>>(pred_boxes, pred_scores, true_boxes, true_classes, pboxes);
    k5_select<<<BB, 512>>>(out);
}

// round 6
// speedup vs baseline: 1.4571x; 1.0166x over previous
#include <cuda_runtime.h>

#define BB 64
#define PP 8732
#define CC 81
#define OO 32
#define NBLK1 35            // ceil(PP/256) match chunks
#define CEB   4366          // (BB*PP)/128 CE tile blocks
#define RPB   128
#define TPB   256
#define TILE_F4 ((RPB * CC) / 4)   // 2592

// ---------------- scratch (static device globals; no allocation) ----------------
__device__ float g_ov[BB*PP];
__device__ int   g_oi[BB*PP];
__device__ float g_lse[BB*PP];                     // log(sum(exp)) per row
__device__ unsigned g_key[BB*PP];                  // orderable-uint CE keys
__device__ unsigned long long g_part[NBLK1*BB*OO]; // per-block argmax partials
__device__ float g_loc_sum;
__device__ int   g_npos;
__device__ float g_cepos;
__device__ float g_hard;
__device__ int   g_done;

// ---------------- helpers ----------------
__device__ __forceinline__ unsigned order_key(float f) {
    unsigned u = __float_as_uint(f);
    return (u & 0x80000000u) ? ~u : (u | 0x80000000u);
}
__device__ __forceinline__ float key_val(unsigned u) {
    u = (u & 0x80000000u) ? (u & 0x7FFFFFFFu) : ~u;
    return __uint_as_float(u);
}

// ---------------- kA: FUSED sum-exp (CE blocks) + IoU matching (match blocks) ----------
// 6720 blocks x 256. bid%3==2 -> match block q=bid/3 (2240 of them);
// else CE block c=2*(bid/3)+(bid%3), active when c<4366. Both types co-resident,
// so matching math hides under the 181MB score stream's memory stalls.
__global__ void __launch_bounds__(TPB, 4) kA_fused(
        const float* __restrict__ scores,
        const float* __restrict__ tb, const float* __restrict__ pbx) {
    __shared__ union {
        float tile[RPB * CC];                         // 41472 B (CE role)
        struct {
            float x0[OO], y0[OO], x1[OO], y1[OO], area[OO];
            unsigned long long best[OO];
        } m;                                          // match role
    } sm;
    int tid = threadIdx.x;
    int r3 = blockIdx.x % 3;
    int q  = blockIdx.x / 3;

    if (r3 == 2) {
        // ---------------- match role: block q in [0,2240) ----------------
        int b  = q / NBLK1;
        int bx = q - b * NBLK1;
        int p  = bx * 256 + tid;
        if (tid < OO) {
            const float* t4 = tb + (size_t)(b*OO + tid) * 4;
            float x0 = t4[0], y0 = t4[1], x1 = t4[2], y1 = t4[3];
            sm.m.x0[tid] = x0; sm.m.y0[tid] = y0;
            sm.m.x1[tid] = x1; sm.m.y1[tid] = y1;
            sm.m.area[tid] = (x1 - x0) * (y1 - y0);
            sm.m.best[tid] = 0ULL;
        }
        __syncthreads();
        bool valid = (p < PP);
        float bx0 = 0, by0 = 0, bx1 = 0, by1 = 0, areab = 0;
        if (valid) {
            const float* pr = pbx + (size_t)p * 4;
            float cx = pr[0], cy = pr[1], w = pr[2], h = pr[3];
            bx0 = cx - 0.5f * w; bx1 = cx + 0.5f * w;
            by0 = cy - 0.5f * h; by1 = cy + 0.5f * h;
            areab = w * h;
        }
        float bestv = -1.f; int besti = 0;
        if (valid) {
            unsigned plow = 0xFFFFFFFFu - (unsigned)p;   // smaller p -> larger low bits
            #pragma unroll 4
            for (int o = 0; o < OO; o++) {
                float lx = fmaxf(sm.m.x0[o], bx0), ly = fmaxf(sm.m.y0[o], by0);
                float rx = fminf(sm.m.x1[o], bx1), ry = fminf(sm.m.y1[o], by1);
                float iw = fmaxf(rx - lx, 0.f), ih = fmaxf(ry - ly, 0.f);
                float inter = iw * ih;
                float uni = sm.m.area[o] + areab - inter;
                float iou = __fdividef(inter, uni);
                if (iou > bestv) { bestv = iou; besti = o; }     // first-index tiebreak
                unsigned long long key =
                    ((unsigned long long)(__float_as_uint(iou) | 0x80000000u) << 32)
                    | (unsigned long long)plow;                  // smaller p wins ties
                if (key > sm.m.best[o]) atomicMax(&sm.m.best[o], key); // guarded: rare
            }
            g_ov[b*PP + p] = bestv;
            g_oi[b*PP + p] = besti;
        }
        __syncthreads();
        if (tid < OO)
            g_part[((size_t)bx * BB + b) * OO + tid] = sm.m.best[tid];
    } else {
        // ---------------- CE role: block c in [0,4480), active < 4366 -----------
        int c = 2 * q + r3;
        if (c >= CEB) return;
        size_t base_f4 = (size_t)c * TILE_F4;
        const float4* src = (const float4*)scores + base_f4;
        float4* dst = (float4*)sm.tile;
        #pragma unroll 4
        for (int i = tid; i < TILE_F4; i += TPB) dst[i] = __ldg(src + i);
        __syncthreads();
        int half = tid & 1;
        int r = tid >> 1;
        const float* my = sm.tile + r * CC;
        int off0 = half * 40;
        float a0 = 0.f, a1 = 0.f, a2 = 0.f, a3 = 0.f;
        #pragma unroll
        for (int j = 0; j < 40; j += 4) {
            a0 += __expf(my[off0 + j]);
            a1 += __expf(my[off0 + j + 1]);
            a2 += __expf(my[off0 + j + 2]);
            a3 += __expf(my[off0 + j + 3]);
        }
        float e = (a0 + a1) + (a2 + a3);
        if (half) e += __expf(my[80]);
        e += __shfl_xor_sync(0xffffffffu, e, 1);      // pair combine
        if (half == 0) g_lse[c * RPB + r] = __logf(e);
    }
}

// ---------------- kB: reduce partials + sequential scatter + zero scalars -------
// grid 2 x 1024: warp = batch, lane = object. All lanes shuffle; lane 0 stores.
__global__ void kB_scatter() {
    if (blockIdx.x == 0 && threadIdx.x == 0) {
        g_loc_sum = 0.f; g_npos = 0; g_cepos = 0.f; g_hard = 0.f; g_done = 0;
    }
    int w = (blockIdx.x * blockDim.x + threadIdx.x) >> 5;
    int o = threadIdx.x & 31;
    if (w >= BB) return;
    int b = w;
    unsigned long long best = 0ULL;
    #pragma unroll 5
    for (int i = 0; i < NBLK1; i++) {
        unsigned long long k = g_part[((size_t)i * BB + b) * OO + o];
        if (k > best) best = k;
    }
    #pragma unroll
    for (int j = 0; j < OO; j++) {
        unsigned long long key = __shfl_sync(0xffffffffu, best, j);
        if (o == 0) {
            unsigned p = 0xFFFFFFFFu - (unsigned)(key & 0xFFFFFFFFull);
            if (p < PP) {
                g_oi[b*PP + p] = j;
                g_ov[b*PP + p] = 1.0f;
            }
        }
    }
}

// ---------------- kC: labels + CE key + loc loss (thread per row) ----------------
__global__ void __launch_bounds__(256) kC_label(
        const float* __restrict__ pred, const float* __restrict__ scores,
        const float* __restrict__ tb, const int* __restrict__ tc,
        const float* __restrict__ pbx) {
    int idx = blockIdx.x * 256 + threadIdx.x;      // 2183*256 == BB*PP exactly
    float ov = g_ov[idx];
    int   oi = g_oi[idx];
    int b = idx / PP;
    int p = idx - b * PP;
    int lab = (ov < 0.5f) ? 0 : __ldg(tc + b*OO + oi);
    float ce = g_lse[idx] - __ldg(scores + (size_t)idx * CC + lab);
    g_key[idx] = order_key(ce);

    float acc = 0.f, l1 = 0.f; int cnt = 0;
    if (lab != 0) {
        acc = ce; cnt = 1;
        const float* t4 = tb + (size_t)(b*OO + oi) * 4;
        float x0 = __ldg(t4), y0 = __ldg(t4+1), x1 = __ldg(t4+2), y1 = __ldg(t4+3);
        const float* pr = pbx + (size_t)p * 4;
        float pcx = __ldg(pr), pcy = __ldg(pr+1), pw = __ldg(pr+2), ph = __ldg(pr+3);
        float gcx = ((x0 + x1) * 0.5f - pcx) * 10.f / pw;
        float gcy = ((y0 + y1) * 0.5f - pcy) * 10.f / ph;
        float gw  = logf((x1 - x0) / pw) * 5.f;
        float gh  = logf((y1 - y0) / ph) * 5.f;
        const float* pd = pred + (size_t)idx * 4;
        l1 = fabsf(pd[0]-gcx) + fabsf(pd[1]-gcy) + fabsf(pd[2]-gw) + fabsf(pd[3]-gh);
    }
    int lane = threadIdx.x & 31, wid = threadIdx.x >> 5;
    #pragma unroll
    for (int off = 16; off; off >>= 1) {
        acc += __shfl_xor_sync(0xffffffffu, acc, off);
        l1  += __shfl_xor_sync(0xffffffffu, l1, off);
        cnt += __shfl_xor_sync(0xffffffffu, cnt, off);
    }
    __shared__ float racc[8], rl1[8]; __shared__ int rcnt[8];
    if (lane == 0) { racc[wid] = acc; rl1[wid] = l1; rcnt[wid] = cnt; }
    __syncthreads();
    if (threadIdx.x == 0) {
        float a = 0.f, l = 0.f; int c = 0;
        #pragma unroll
        for (int i = 0; i < 8; i++) { a += racc[i]; l += rl1[i]; c += rcnt[i]; }
        if (a != 0.f) atomicAdd(&g_cepos, a);
        if (l != 0.f) atomicAdd(&g_loc_sum, l);
        if (c)        atomicAdd(&g_npos, c);
    }
}

// ---------------- kD: per-row top-k via radix select (parallel bin scan) --------
__global__ void kD_select(float* __restrict__ out) {
    __shared__ unsigned skeys[PP];
    __shared__ int bins[256];
    __shared__ int suf[256];
    __shared__ unsigned sh_pref;
    __shared__ int sh_rem;
    __shared__ float swsum[16];
    __shared__ int swcnt[16];
    int r = blockIdx.x;
    int tid = threadIdx.x;
    const int bd = 512;
    int lane = tid & 31, wid = tid >> 5;

    // uint4 loads: PP = 4*2183, row base 16B-aligned
    {
        const uint4* src = (const uint4*)(g_key + (size_t)r * PP);
        uint4* dst = (uint4*)skeys;
        for (int i = tid; i < PP/4; i += bd) dst[i] = src[i];
    }
    __syncthreads();
    int np = g_npos;
    long long k = 3LL * (long long)np;
    const int NITER = (PP + bd - 1) / bd;    // 18 (warp-uniform padded)

    float total = 0.f;
    if (k >= PP) {
        float sv = 0.f;
        for (int p = tid; p < PP; p += bd) sv += key_val(skeys[p]);
        #pragma unroll
        for (int off = 16; off; off >>= 1) sv += __shfl_xor_sync(0xffffffffu, sv, off);
        if (lane == 0) swsum[wid] = sv;
        __syncthreads();
        if (tid == 0) for (int i = 0; i < bd/32; i++) total += swsum[i];
    } else if (k > 0) {
        unsigned prefix = 0; int rem = (int)k;
        for (int shift = 24; shift >= 0; shift -= 8) {
            if (tid < 256) bins[tid] = 0;
            __syncthreads();
            unsigned hi_mask = (shift == 24) ? 0u : (0xFFFFFFFFu << (shift + 8));
            for (int it = 0; it < NITER; it++) {
                int p = tid + it * bd;
                bool in = (p < PP);
                unsigned key = in ? skeys[p] : 0u;
                bool act = in && ((key & hi_mask) == prefix);
                unsigned bm = __ballot_sync(0xffffffffu, act);
                if (act) {
                    unsigned bin = (key >> shift) & 255u;
                    unsigned peers = __match_any_sync(bm, bin);
                    int leader = __ffs(peers) - 1;
                    if (lane == leader) atomicAdd(&bins[bin], __popc(peers));
                }
            }
            __syncthreads();
            // parallel inclusive SUFFIX scan of bins (suf[i] = sum_{j>=i} bins[j])
            if (tid < 256) suf[tid] = bins[tid];
            __syncthreads();
            #pragma unroll
            for (int off = 1; off < 256; off <<= 1) {
                int v = 0;
                if (tid < 256) v = suf[tid] + ((tid + off < 256) ? suf[tid + off] : 0);
                __syncthreads();
                if (tid < 256) suf[tid] = v;
                __syncthreads();
            }
            if (tid < 256) {
                int here  = suf[tid];
                int above = (tid < 255) ? suf[tid + 1] : 0;
                if (here >= rem && above < rem) {        // exactly one tid matches
                    sh_pref = prefix | ((unsigned)tid << shift);
                    sh_rem  = rem - above;
                }
            }
            __syncthreads();
            prefix = sh_pref; rem = sh_rem;
            __syncthreads();
        }
        unsigned kth = prefix;  // exact k-th largest key
        float sumv = 0.f; int cgt = 0;
        for (int p = tid; p < PP; p += bd) {
            unsigned key = skeys[p];
            if (key > kth) { sumv += key_val(key); cgt++; }
        }
        #pragma unroll
        for (int off = 16; off; off >>= 1) {
            sumv += __shfl_xor_sync(0xffffffffu, sumv, off);
            cgt  += __shfl_xor_sync(0xffffffffu, cgt, off);
        }
        if (lane == 0) { swsum[wid] = sumv; swcnt[wid] = cgt; }
        __syncthreads();
        if (tid == 0) {
            float t = 0.f; int c = 0;
            for (int i = 0; i < bd/32; i++) { t += swsum[i]; c += swcnt[i]; }
            total = t + (float)(k - c) * key_val(kth);   // exact tie handling
        }
    }

    if (tid == 0) {
        if (total != 0.f) atomicAdd(&g_hard, total);
        __threadfence();
        int ticket = atomicAdd(&g_done, 1);
        if (ticket == BB - 1) {                          // last block finalizes
            float hard = atomicAdd(&g_hard, 0.f);
            float npf = (float)np;
            out[0] = g_loc_sum / (npf * 4.f) + (g_cepos + hard) / npf;
        }
    }
}

// ---------------- launch ----------------
extern "C" void kernel_launch(void* const* d_in, const int* in_sizes, int n_in,
                              void* d_out, int out_size) {
    const float* pred_boxes   = (const float*)d_in[0];
    const float* pred_scores  = (const float*)d_in[1];
    const float* true_boxes   = (const float*)d_in[2];
    const int*   true_classes = (const int*)d_in[3];
    const float* pboxes       = (const float*)d_in[4];
    float* out = (float*)d_out;
    (void)in_sizes; (void)n_in; (void)out_size;

    kA_fused<<<6720, TPB>>>(pred_scores, true_boxes, pboxes);
    kB_scatter<<<2, 1024>>>();
    kC_label<<<(BB*PP)/256, 256>>>(pred_boxes, pred_scores, true_boxes, true_classes, pboxes);
    kD_select<<<BB, 512>>>(out);
}